// round 10
// baseline (speedup 1.0000x reference)
#include <cuda_runtime.h>
#include <cstdint>

#define HH 1536
#define WW 2048
#define NN (HH*WW)
#define WPR 64                 // 32-bit words per row
#define CAP 512                // max dilated runs per row (period >= 4)
#define RPB 8                  // rows per block in k_runs
#define NSLOT (HH*CAP)
#define MAXROOTS 65536

// scratch (device globals: allocation-free rule)
__device__ uint32_t g_comb[HH * WPR];   // comb bitmap
__device__ uint32_t g_text[HH * WPR];   // text bitmap
__device__ int g_rxs[NSLOT];            // run x-start
__device__ int g_rxe[NSLOT];            // run x-end (inclusive)
__device__ int g_runcnt[HH];
__device__ int g_rpar[NSLOT];           // union-find over run slots (min-ordered)
__device__ int g_rxmin[NSLOT];          // bbox fields: only block-local roots populated
__device__ int g_rxmax[NSLOT];
__device__ int g_rymax[NSLOT];
__device__ int g_rtext[NSLOT];
__device__ int g_roots[MAXROOTS];       // block-local roots (global sids)
__device__ int g_nroots;

// ---------------- concurrent min-union-find over global run slots ----------------
// invariant: parent[i] <= i, parent[i] in i's component. All writes are atomicMin
// (unions AND path-halving) -> safe under full concurrency; root = component min.
__device__ __forceinline__ int uf_find(int i) {
    int n = __ldcg(&g_rpar[i]);
    while (n != i) {
        int g = __ldcg(&g_rpar[n]);
        if (g != n) atomicMin(&g_rpar[i], g);   // halve
        i = n; n = g;
    }
    return i;
}
__device__ __forceinline__ void uf_union(int a, int b) {
    while (true) {
        a = uf_find(a);
        b = uf_find(b);
        if (a == b) return;
        int lo = min(a, b), hi = max(a, b);
        int old = atomicMin(&g_rpar[hi], lo);
        if (old == hi) return;
        a = lo; b = old;
    }
}

// ---------------- smem union-find (min-ordered) ----------------
__device__ __forceinline__ int sfind(volatile int* L, int i) {
    int n;
    while ((n = L[i]) != i) i = n;
    return i;
}
__device__ __forceinline__ void sunite(int* L, int a, int b) {
    volatile int* V = L;
    while (true) {
        a = sfind(V, a);
        b = sfind(V, b);
        if (a == b) return;
        int lo = min(a, b), hi = max(a, b);
        int old = atomicMin(&L[hi], lo);
        if (old == hi) return;
        a = lo; b = old;
    }
}

// ---------------- pass 1: zero output + threshold -> bitmaps + reset ----------------
__global__ void k_prep(const float* __restrict__ x, float* __restrict__ out,
                       int n4, int out_size) {
    int gid = blockIdx.x * blockDim.x + threadIdx.x;
    if (gid == 0) g_nroots = 0;
    if (gid < n4) ((float4*)out)[gid] = make_float4(0.f, 0.f, 0.f, 0.f);
    int base = n4 * 4 + gid;
    if (base < out_size) out[base] = 0.f;        // tail (normally empty)
    if (gid < NN) {
        float2 p = ((const float2*)x)[gid];
        unsigned cb = __ballot_sync(0xffffffffu, (p.x > 0.4f) | (p.y > 0.4f));
        unsigned tb = __ballot_sync(0xffffffffu, p.x > 0.4f);
        if ((threadIdx.x & 31) == 0) {
            g_comb[gid >> 5] = cb;
            g_text[gid >> 5] = tb;
        }
    }
}

// ---------------- pass 2: dilate + runs + block-local CCL + local fold ----------------
__global__ void __launch_bounds__(256) k_runs() {
    __shared__ uint32_t sv[RPB][WPR + 2];   // vertical OR, sentinels
    __shared__ uint32_t sd[RPB][WPR];       // dilated row
    __shared__ uint32_t st[RPB][WPR];       // text row
    __shared__ int spar[RPB * CAP];         // local UF parents
    __shared__ int sxsxe[RPB * CAP];        // xs | xe<<16
    __shared__ unsigned char stxt[RPB * CAP];
    __shared__ int scnt[RPB];

    int tid = threadIdx.x;
    int wid = tid >> 5, lane = tid & 31;
    int y = blockIdx.x * RPB + wid;
    int ybase = blockIdx.x * RPB;

    const uint32_t* rm = (y > 0) ? &g_comb[(y - 1) * WPR] : nullptr;
    const uint32_t* rc = &g_comb[y * WPR];
    const uint32_t* rp = (y < HH - 1) ? &g_comb[(y + 1) * WPR] : nullptr;

    if (lane == 0) { sv[wid][0] = 0; sv[wid][WPR + 1] = 0; }
#pragma unroll
    for (int k = 0; k < 2; k++) {
        int w = lane + k * 32;
        uint32_t v = rc[w];
        if (rm) v |= rm[w];
        if (rp) v |= rp[w];
        sv[wid][1 + w] = v;
        st[wid][w] = g_text[y * WPR + w];
    }
    __syncwarp();
#pragma unroll
    for (int k = 0; k < 2; k++) {
        int w = lane + k * 32;
        uint32_t v = sv[wid][1 + w];
        sd[wid][w] = v | (v << 1) | (v >> 1)
                   | (sv[wid][w] >> 31) | (sv[wid][2 + w] << 31);
    }
    __syncwarp();

    // serial run extraction per row (lane 0), ~2 runs/row expected
    if (lane == 0) {
        int cnt = 0;
        bool open = false;
        int xs = 0;
        unsigned tacc = 0;
        for (int w = 0; w <= WPR; w++) {
            unsigned b = (w < WPR) ? sd[wid][w] : 0u;
            unsigned t = (w < WPR) ? st[wid][w] : 0u;
            int pos = 0;
            while (true) {
                if (!open) {
                    unsigned rem = b >> pos;
                    if (!rem) break;
                    int s = pos + __ffs(rem) - 1;
                    xs = w * 32 + s; tacc = 0; open = true; pos = s;
                } else {
                    unsigned rem = (~b) >> pos;
                    if (!rem) {
                        tacc |= t & (0xffffffffu << pos);
                        break;
                    }
                    int e = pos + __ffs(rem) - 1;
                    tacc |= t & (((1u << e) - 1) & ~((1u << pos) - 1));
                    int xe = w * 32 + e - 1;
                    int ls = wid * CAP + cnt;
                    spar[ls] = ls;
                    sxsxe[ls] = xs | (xe << 16);
                    stxt[ls] = (tacc != 0);
                    int sid = y * CAP + cnt;
                    g_rxs[sid] = xs;        // needed for boundary linking
                    g_rxe[sid] = xe;
                    cnt++;
                    open = false; pos = e;
                    if (pos >= 32) break;
                }
            }
        }
        scnt[wid] = cnt;
        g_runcnt[y] = cnt;
    }
    __syncthreads();

    // local link: interior row pairs (wid, wid+1)
    if (tid < RPB - 1) {
        int ca = scnt[tid], cb = scnt[tid + 1];
        int i = 0, j = 0;
        int ab = tid * CAP, bb = (tid + 1) * CAP;
        while (i < ca && j < cb) {
            int A = sxsxe[ab + i], B = sxsxe[bb + j];
            int axs = A & 0xffff, axe = A >> 16;
            int bxs = B & 0xffff, bxe = B >> 16;
            if (axs <= bxe && bxs <= axe) sunite(spar, ab + i, bb + j);
            if (axe < bxe) i++; else j++;
        }
    }
    __syncthreads();

    // publish: every run points 1 hop to its local root; local roots init their
    // global bbox slot (own run's bbox) and join the roots list
    for (int ls = tid; ls < RPB * CAP; ls += 256) {
        int w = ls >> 9, k = ls & (CAP - 1);
        if (k >= scnt[w]) continue;
        int lr = sfind(spar, ls);
        int yw = ybase + w;
        int sid = yw * CAP + k;
        int lr_sid = (ybase + (lr >> 9)) * CAP + (lr & (CAP - 1));
        g_rpar[sid] = lr_sid;
        if (ls == lr) {
            int xsv = sxsxe[ls] & 0xffff, xev = sxsxe[ls] >> 16;
            g_rxmin[sid] = xsv;
            g_rxmax[sid] = xev;
            g_rymax[sid] = yw;
            g_rtext[sid] = stxt[ls];
            int slot = atomicAdd(&g_nroots, 1);
            g_roots[slot] = sid;
        }
    }
    __syncthreads();

    // fold non-root runs into their local root's global bbox (init visible: sync)
    for (int ls = tid; ls < RPB * CAP; ls += 256) {
        int w = ls >> 9, k = ls & (CAP - 1);
        if (k >= scnt[w]) continue;
        int lr = sfind(spar, ls);
        if (lr == ls) continue;
        int yw = ybase + w;
        int lr_sid = (ybase + (lr >> 9)) * CAP + (lr & (CAP - 1));
        int xsv = sxsxe[ls] & 0xffff, xev = sxsxe[ls] >> 16;
        atomicMin(&g_rxmin[lr_sid], xsv);
        atomicMax(&g_rxmax[lr_sid], xev);
        atomicMax(&g_rymax[lr_sid], yw);
        if (stxt[ls]) atomicMax(&g_rtext[lr_sid], 1);
    }
}

// ---------------- pass 3 (single block): boundary link + fold + emit ----------------
__global__ void __launch_bounds__(256) k_final(float* __restrict__ out) {
    int tid = threadIdx.x;

    // phase 1: link runs across block boundaries (rows 8t+7 / 8t+8)
    for (int t = tid; t < HH / RPB - 1; t += 256) {
        int ya = t * RPB + (RPB - 1), yb = ya + 1;
        int ca = g_runcnt[ya], cb = g_runcnt[yb];
        int i = 0, j = 0;
        int ab = ya * CAP, bb = yb * CAP;
        while (i < ca && j < cb) {
            int axs = g_rxs[ab + i], axe = g_rxe[ab + i];
            int bxs = g_rxs[bb + j], bxe = g_rxe[bb + j];
            if (axs <= bxe && bxs <= axe) uf_union(ab + i, bb + j);
            if (axe < bxe) i++; else j++;
        }
    }
    __syncthreads();

    // phase 2: fold block-local roots into final roots
    int nr = g_nroots;
    for (int j = tid; j < nr; j += 256) {
        int r = g_roots[j];
        int f = uf_find(r);
        if (f == r) continue;
        atomicMin(&g_rxmin[f], g_rxmin[r]);
        atomicMax(&g_rxmax[f], g_rxmax[r]);
        atomicMax(&g_rymax[f], g_rymax[r]);
        if (g_rtext[r]) atomicMax(&g_rtext[f], 1);
    }
    __syncthreads();

    // phase 3: emit final roots
    for (int j = tid; j < nr; j += 256) {
        int r = g_roots[j];
        if (__ldcg(&g_rpar[r]) != r) continue;   // final root = component min run
        int y = r >> 9;                           // r / CAP
        int xs = g_rxs[r];
        int flat = y * WW + xs;                   // component min flat index
        int h = g_rymax[r] - y;
        int w = g_rxmax[r] - g_rxmin[r];
        if (h > 4 && w > 4 && g_rtext[r]) {
            ((float4*)out)[flat] = make_float4((float)y, (float)g_rxmin[r],
                                               (float)h, (float)w);
            out[4 * NN + flat] = 1.0f;
        }
    }
}

extern "C" void kernel_launch(void* const* d_in, const int* in_sizes, int n_in,
                              void* d_out, int out_size) {
    const float* x = (const float*)d_in[0];
    float* out = (float*)d_out;

    int n4 = out_size / 4;
    int nprep_threads = (n4 > NN) ? n4 : NN;
    k_prep<<<(nprep_threads + 255) / 256, 256>>>(x, out, n4, out_size);
    k_runs<<<HH / RPB, 256>>>();
    k_final<<<1, 256>>>(out);
}